// round 12
// baseline (speedup 1.0000x reference)
#include <cuda_runtime.h>

// SpatialTransformer: vol [B=2,192,192,192,1] fp32, affine [B,3,4] fp32.
// Warp = 32 consecutive w; 4 voxels/thread along h (UH=4 keeps 32 regs and
// ~84% occupancy — the UH=8 variant lost occupancy and was latency-bound).
// Three warp-uniform paths:
//   A: d,h,w all strictly interior -> no clamps/selects, 8 gathers at
//      compile-time immediate offsets off ONE base pointer.
//   B: d,h interior, w general.
//   C: fully general (exact reference clamp semantics).
// Affine read directly from gmem (no memcpy graph node).

#define DIM 192
#define SLAB (DIM * DIM)
#define BATCH 2
#define UH 4

__global__ __launch_bounds__(DIM) void st_warp3b(
    const float* __restrict__ vol,
    const float* __restrict__ aff,
    float* __restrict__ out)
{
    const int w  = threadIdx.x;             // warp = 32 consecutive w
    const int h0 = blockIdx.x * UH;
    const int d  = blockIdx.y;
    const int b  = blockIdx.z;

    const float ctr  = (DIM - 1) * 0.5f;    // 95.5
    const float maxl = (float)(DIM - 1);    // 191

    const float* A = aff + b * 12;          // warp-uniform, L1-hit
    const float a00 = __ldg(A + 0), a01 = __ldg(A + 1),  a02 = __ldg(A + 2),  a03 = __ldg(A + 3);
    const float a10 = __ldg(A + 4), a11 = __ldg(A + 5),  a12 = __ldg(A + 6),  a13 = __ldg(A + 7);
    const float a20 = __ldg(A + 8), a21 = __ldg(A + 9),  a22 = __ldg(A + 10), a23 = __ldg(A + 11);

    const float cd = (float)d  - ctr;
    const float ch = (float)h0 - ctr;
    const float cw = (float)w  - ctr;

    // Sample location at j=0; along h it advances by (a01, a11, a21)/voxel.
    const float ld0 = fmaf(a00, cd, fmaf(a01, ch, fmaf(a02, cw, a03))) + ctr;
    const float lh0 = fmaf(a10, cd, fmaf(a11, ch, fmaf(a12, cw, a13))) + ctr;
    const float lw0 = fmaf(a20, cd, fmaf(a21, ch, fmaf(a22, cw, a23))) + ctr;

    const float* vb = vol + (size_t)b * (DIM * SLAB);
    float* ob = out + ((size_t)(b * DIM + d) * DIM + h0) * DIM + w;

    // ---- warp-uniform interior tests (separable corner extrema) ----
    const int   wlo = w & ~31;
    const float chl = (float)h0 - ctr,  chh = (float)(h0 + UH - 1) - ctr;
    const float cwl = (float)wlo - ctr, cwh = (float)(wlo + 31) - ctr;

    const float bas_d = a00 * cd + a03 + ctr;
    const float lo_d  = bas_d + fminf(a01 * chl, a01 * chh) + fminf(a02 * cwl, a02 * cwh);
    const float hi_d  = bas_d + fmaxf(a01 * chl, a01 * chh) + fmaxf(a02 * cwl, a02 * cwh);
    const float bas_h = a10 * cd + a13 + ctr;
    const float lo_h  = bas_h + fminf(a11 * chl, a11 * chh) + fminf(a12 * cwl, a12 * cwh);
    const float hi_h  = bas_h + fmaxf(a11 * chl, a11 * chh) + fmaxf(a12 * cwl, a12 * cwh);
    const float bas_w = a20 * cd + a23 + ctr;
    const float lo_w  = bas_w + fminf(a21 * chl, a21 * chh) + fminf(a22 * cwl, a22 * cwh);
    const float hi_w  = bas_w + fmaxf(a21 * chl, a21 * chh) + fmaxf(a22 * cwl, a22 * cwh);

    // 0.5 guard >> fp discrepancy (~1e-4) between extrema and fma chains.
    const bool dh_int = (lo_d > 0.5f) & (hi_d < 190.5f) &
                        (lo_h > 0.5f) & (hi_h < 190.5f);
    const bool w_int  = (lo_w > 0.5f) & (hi_w < 190.5f);

    if (dh_int & w_int) {
        // ---- path A: fully interior, single base, immediate offsets ----
#pragma unroll
        for (int j = 0; j < UH; j++) {
            const float fj = (float)j;
            const float ldv = fmaf(a01, fj, ld0);
            const float lhv = fmaf(a11, fj, lh0);
            const float lwv = fmaf(a21, fj, lw0);

            const int   id = (int)ldv;  const float td = ldv - (float)id;
            const int   ih = (int)lhv;  const float th = lhv - (float)ih;
            const int   iw = (int)lwv;  const float tw = lwv - (float)iw;

            const float* p = vb + (id * SLAB + ih * DIM + iw);

            const float v000 = __ldg(p);
            const float v001 = __ldg(p + 1);
            const float v010 = __ldg(p + DIM);
            const float v011 = __ldg(p + DIM + 1);
            const float v100 = __ldg(p + SLAB);
            const float v101 = __ldg(p + SLAB + 1);
            const float v110 = __ldg(p + SLAB + DIM);
            const float v111 = __ldg(p + SLAB + DIM + 1);

            const float p00 = fmaf(tw, v001 - v000, v000);
            const float p01 = fmaf(tw, v011 - v010, v010);
            const float p10 = fmaf(tw, v101 - v100, v100);
            const float p11 = fmaf(tw, v111 - v110, v110);
            const float q0  = fmaf(th, p01 - p00, p00);
            const float q1  = fmaf(th, p11 - p10, p10);

            ob[(size_t)j * DIM] = fmaf(td, q1 - q0, q0);
        }
    } else if (dh_int) {
        // ---- path B: d,h interior; w general (handles w edges) ----
#pragma unroll
        for (int j = 0; j < UH; j++) {
            const float fj = (float)j;
            const float ldv = fmaf(a01, fj, ld0);
            const float lhv = fmaf(a11, fj, lh0);
            const float lwv = fmaf(a21, fj, lw0);

            const int   id = (int)ldv;  const float td = ldv - (float)id;
            const int   ih = (int)lhv;  const float th = lhv - (float)ih;

            const float sw = fminf(fmaxf(lwv, 0.f), maxl);
            const int   iw = (int)sw;
            const float tw = sw - (float)iw;
            const int   ow = (iw < DIM - 1) ? 1 : 0;

            const float* p  = vb + (id * SLAB + ih * DIM + iw);
            const float* p2 = p + ow;

            const float v000 = __ldg(p);
            const float v001 = __ldg(p2);
            const float v010 = __ldg(p  + DIM);
            const float v011 = __ldg(p2 + DIM);
            const float v100 = __ldg(p  + SLAB);
            const float v101 = __ldg(p2 + SLAB);
            const float v110 = __ldg(p  + SLAB + DIM);
            const float v111 = __ldg(p2 + SLAB + DIM);

            const float p00 = fmaf(tw, v001 - v000, v000);
            const float p01 = fmaf(tw, v011 - v010, v010);
            const float p10 = fmaf(tw, v101 - v100, v100);
            const float p11 = fmaf(tw, v111 - v110, v110);
            const float q0  = fmaf(th, p01 - p00, p00);
            const float q1  = fmaf(th, p11 - p10, p10);

            ob[(size_t)j * DIM] = fmaf(td, q1 - q0, q0);
        }
    } else {
        // ---- path C: fully general (exact reference clamp semantics) ----
#pragma unroll
        for (int j = 0; j < UH; j++) {
            const float fj = (float)j;
            const float ldv = fmaf(a01, fj, ld0);
            const float lhv = fmaf(a11, fj, lh0);
            const float lwv = fmaf(a21, fj, lw0);

            const float sd = fminf(fmaxf(ldv, 0.f), maxl);
            const int   id = (int)sd;
            const float td = sd - (float)id;
            const int   od = (id < DIM - 1) ? SLAB : 0;

            const float sh = fminf(fmaxf(lhv, 0.f), maxl);
            const int   ih = (int)sh;
            const float th = sh - (float)ih;
            const int   oh = (ih < DIM - 1) ? DIM : 0;

            const float sw = fminf(fmaxf(lwv, 0.f), maxl);
            const int   iw = (int)sw;
            const float tw = sw - (float)iw;
            const int   ow = (iw < DIM - 1) ? 1 : 0;

            const float* p = vb + (id * SLAB + ih * DIM + iw);

            const float v000 = __ldg(p);
            const float v001 = __ldg(p + ow);
            const float v010 = __ldg(p + oh);
            const float v011 = __ldg(p + oh + ow);
            const float* q = p + od;
            const float v100 = __ldg(q);
            const float v101 = __ldg(q + ow);
            const float v110 = __ldg(q + oh);
            const float v111 = __ldg(q + oh + ow);

            const float p00 = fmaf(tw, v001 - v000, v000);
            const float p01 = fmaf(tw, v011 - v010, v010);
            const float p10 = fmaf(tw, v101 - v100, v100);
            const float p11 = fmaf(tw, v111 - v110, v110);
            const float q0  = fmaf(th, p01 - p00, p00);
            const float q1  = fmaf(th, p11 - p10, p10);

            ob[(size_t)j * DIM] = fmaf(td, q1 - q0, q0);
        }
    }
}

extern "C" void kernel_launch(void* const* d_in, const int* in_sizes, int n_in,
                              void* d_out, int out_size)
{
    const float* vol = (const float*)d_in[0];
    const float* aff = (const float*)d_in[1];
    float* out = (float*)d_out;

    dim3 grid(DIM / UH, DIM, BATCH);   // (48, 192, 2)
    dim3 block(DIM);                   // 192 threads, warp = 32 consecutive w
    st_warp3b<<<grid, block>>>(vol, aff, out);
}

// round 14
// speedup vs baseline: 1.0762x; 1.0762x over previous
#include <cuda_runtime.h>

// SpatialTransformer: vol [B=2,192,192,192,1] fp32, affine [B,3,4] fp32.
// R5 body (proven fastest kernel: two warp-uniform paths, UH=4, 32 regs,
// warp = 32 consecutive w) + affine loaded as 3x float4 broadcast LDG.128
// (vs 12 scalar LDGs in R7, which inflated L1 wavefronts ~19%, or the
// __constant__ memcpy graph node in R5, which cost ~6us of total time).

#define DIM 192
#define SLAB (DIM * DIM)
#define BATCH 2
#define UH 4

__global__ __launch_bounds__(DIM) void st_warp_f4(
    const float* __restrict__ vol,
    const float* __restrict__ aff,
    float* __restrict__ out)
{
    const int w  = threadIdx.x;             // warp = 32 consecutive w
    const int h0 = blockIdx.x * UH;
    const int d  = blockIdx.y;
    const int b  = blockIdx.z;

    const float ctr  = (DIM - 1) * 0.5f;    // 95.5
    const float maxl = (float)(DIM - 1);    // 191

    // Affine: 3 broadcast LDG.128 (aff + b*12 floats is 16B-aligned).
    const float4* A4 = (const float4*)(aff + b * 12);
    const float4 r0 = __ldg(A4 + 0);
    const float4 r1 = __ldg(A4 + 1);
    const float4 r2 = __ldg(A4 + 2);
    const float a00 = r0.x, a01 = r0.y, a02 = r0.z, a03 = r0.w;
    const float a10 = r1.x, a11 = r1.y, a12 = r1.z, a13 = r1.w;
    const float a20 = r2.x, a21 = r2.y, a22 = r2.z, a23 = r2.w;

    const float cd = (float)d  - ctr;
    const float ch = (float)h0 - ctr;
    const float cw = (float)w  - ctr;

    // Sample location at j=0; along h it advances by (a01, a11, a21)/voxel.
    const float ld0 = fmaf(a00, cd, fmaf(a01, ch, fmaf(a02, cw, a03))) + ctr;
    const float lh0 = fmaf(a10, cd, fmaf(a11, ch, fmaf(a12, cw, a13))) + ctr;
    const float lw0 = fmaf(a20, cd, fmaf(a21, ch, fmaf(a22, cw, a23))) + ctr;

    const float* vb = vol + (size_t)b * (DIM * SLAB);
    float* ob = out + ((size_t)(b * DIM + d) * DIM + h0) * DIM + w;

    // ---- warp-uniform interior test for d,h dims (separable extrema) ----
    const int   wlo = w & ~31;
    const float chl = (float)h0 - ctr,  chh = (float)(h0 + UH - 1) - ctr;
    const float cwl = (float)wlo - ctr, cwh = (float)(wlo + 31) - ctr;

    const float bas_d = a00 * cd + a03 + ctr;
    const float lo_d  = bas_d + fminf(a01 * chl, a01 * chh) + fminf(a02 * cwl, a02 * cwh);
    const float hi_d  = bas_d + fmaxf(a01 * chl, a01 * chh) + fmaxf(a02 * cwl, a02 * cwh);
    const float bas_h = a10 * cd + a13 + ctr;
    const float lo_h  = bas_h + fminf(a11 * chl, a11 * chh) + fminf(a12 * cwl, a12 * cwh);
    const float hi_h  = bas_h + fmaxf(a11 * chl, a11 * chh) + fmaxf(a12 * cwl, a12 * cwh);

    // 0.5 guard >> fp discrepancy (~1e-4) between extrema and fma chains.
    const bool fast = (lo_d > 0.5f) & (hi_d < 190.5f) &
                      (lo_h > 0.5f) & (hi_h < 190.5f);

    if (fast) {
        // ---- fast path: d,h interior; w fully general ----
#pragma unroll
        for (int j = 0; j < UH; j++) {
            const float fj = (float)j;
            const float ldv = fmaf(a01, fj, ld0);
            const float lhv = fmaf(a11, fj, lh0);
            const float lwv = fmaf(a21, fj, lw0);

            const int   id = (int)ldv;  const float td = ldv - (float)id;
            const int   ih = (int)lhv;  const float th = lhv - (float)ih;

            const float sw = fminf(fmaxf(lwv, 0.f), maxl);
            const int   iw = (int)sw;
            const float tw = sw - (float)iw;
            const int   ow = (iw < DIM - 1) ? 1 : 0;

            const float* p  = vb + (id * SLAB + ih * DIM + iw);
            const float* p2 = p + ow;

            const float v000 = __ldg(p);
            const float v001 = __ldg(p2);
            const float v010 = __ldg(p  + DIM);
            const float v011 = __ldg(p2 + DIM);
            const float v100 = __ldg(p  + SLAB);
            const float v101 = __ldg(p2 + SLAB);
            const float v110 = __ldg(p  + SLAB + DIM);
            const float v111 = __ldg(p2 + SLAB + DIM);

            const float p00 = fmaf(tw, v001 - v000, v000);
            const float p01 = fmaf(tw, v011 - v010, v010);
            const float p10 = fmaf(tw, v101 - v100, v100);
            const float p11 = fmaf(tw, v111 - v110, v110);
            const float q0  = fmaf(th, p01 - p00, p00);
            const float q1  = fmaf(th, p11 - p10, p10);

            ob[(size_t)j * DIM] = fmaf(td, q1 - q0, q0);
        }
    } else {
        // ---- general path: exact reference clamp semantics every dim ----
#pragma unroll
        for (int j = 0; j < UH; j++) {
            const float fj = (float)j;
            const float ldv = fmaf(a01, fj, ld0);
            const float lhv = fmaf(a11, fj, lh0);
            const float lwv = fmaf(a21, fj, lw0);

            const float sd = fminf(fmaxf(ldv, 0.f), maxl);
            const int   id = (int)sd;
            const float td = sd - (float)id;
            const int   od = (id < DIM - 1) ? SLAB : 0;

            const float sh = fminf(fmaxf(lhv, 0.f), maxl);
            const int   ih = (int)sh;
            const float th = sh - (float)ih;
            const int   oh = (ih < DIM - 1) ? DIM : 0;

            const float sw = fminf(fmaxf(lwv, 0.f), maxl);
            const int   iw = (int)sw;
            const float tw = sw - (float)iw;
            const int   ow = (iw < DIM - 1) ? 1 : 0;

            const float* p = vb + (id * SLAB + ih * DIM + iw);

            const float v000 = __ldg(p);
            const float v001 = __ldg(p + ow);
            const float v010 = __ldg(p + oh);
            const float v011 = __ldg(p + oh + ow);
            const float* q = p + od;
            const float v100 = __ldg(q);
            const float v101 = __ldg(q + ow);
            const float v110 = __ldg(q + oh);
            const float v111 = __ldg(q + oh + ow);

            const float p00 = fmaf(tw, v001 - v000, v000);
            const float p01 = fmaf(tw, v011 - v010, v010);
            const float p10 = fmaf(tw, v101 - v100, v100);
            const float p11 = fmaf(tw, v111 - v110, v110);
            const float q0  = fmaf(th, p01 - p00, p00);
            const float q1  = fmaf(th, p11 - p10, p10);

            ob[(size_t)j * DIM] = fmaf(td, q1 - q0, q0);
        }
    }
}

extern "C" void kernel_launch(void* const* d_in, const int* in_sizes, int n_in,
                              void* d_out, int out_size)
{
    const float* vol = (const float*)d_in[0];
    const float* aff = (const float*)d_in[1];
    float* out = (float*)d_out;

    dim3 grid(DIM / UH, DIM, BATCH);   // (48, 192, 2)
    dim3 block(DIM);                   // 192 threads, warp = 32 consecutive w
    st_warp_f4<<<grid, block>>>(vol, aff, out);
}

// round 15
// speedup vs baseline: 1.0903x; 1.0131x over previous
#include <cuda_runtime.h>

// SpatialTransformer: vol [B=2,192,192,192,1] fp32, affine [B,3,4] fp32.
// Warp = 32 consecutive w (4B lane stride -> ~2 lines per gather); UH=6
// voxels/thread along h to amortize the prologue; two warp-uniform paths:
//   fast: d,h strictly interior -> no clamp/select for d,h, immediate-offset
//         gathers off two bases (w stays fully general).
//   general: exact reference clamp semantics in all dims.
// Affine loaded as 3x broadcast LDG.128 (no memcpy graph node).

#define DIM 192
#define SLAB (DIM * DIM)
#define BATCH 2
#define UH 6

__global__ __launch_bounds__(DIM) void st_warp_u6(
    const float* __restrict__ vol,
    const float* __restrict__ aff,
    float* __restrict__ out)
{
    const int w  = threadIdx.x;             // warp = 32 consecutive w
    const int h0 = blockIdx.x * UH;
    const int d  = blockIdx.y;
    const int b  = blockIdx.z;

    const float ctr  = (DIM - 1) * 0.5f;    // 95.5
    const float maxl = (float)(DIM - 1);    // 191

    // Affine: 3 broadcast LDG.128 (aff + b*12 floats is 16B-aligned).
    const float4* A4 = (const float4*)(aff + b * 12);
    const float4 r0 = __ldg(A4 + 0);
    const float4 r1 = __ldg(A4 + 1);
    const float4 r2 = __ldg(A4 + 2);
    const float a00 = r0.x, a01 = r0.y, a02 = r0.z, a03 = r0.w;
    const float a10 = r1.x, a11 = r1.y, a12 = r1.z, a13 = r1.w;
    const float a20 = r2.x, a21 = r2.y, a22 = r2.z, a23 = r2.w;

    const float cd = (float)d  - ctr;
    const float ch = (float)h0 - ctr;
    const float cw = (float)w  - ctr;

    // Sample location at j=0; along h it advances by (a01, a11, a21)/voxel.
    const float ld0 = fmaf(a00, cd, fmaf(a01, ch, fmaf(a02, cw, a03))) + ctr;
    const float lh0 = fmaf(a10, cd, fmaf(a11, ch, fmaf(a12, cw, a13))) + ctr;
    const float lw0 = fmaf(a20, cd, fmaf(a21, ch, fmaf(a22, cw, a23))) + ctr;

    const float* vb = vol + (size_t)b * (DIM * SLAB);
    float* ob = out + ((size_t)(b * DIM + d) * DIM + h0) * DIM + w;

    // ---- warp-uniform interior test for d,h dims (separable extrema) ----
    const int   wlo = w & ~31;
    const float chl = (float)h0 - ctr,  chh = (float)(h0 + UH - 1) - ctr;
    const float cwl = (float)wlo - ctr, cwh = (float)(wlo + 31) - ctr;

    const float bas_d = a00 * cd + a03 + ctr;
    const float lo_d  = bas_d + fminf(a01 * chl, a01 * chh) + fminf(a02 * cwl, a02 * cwh);
    const float hi_d  = bas_d + fmaxf(a01 * chl, a01 * chh) + fmaxf(a02 * cwl, a02 * cwh);
    const float bas_h = a10 * cd + a13 + ctr;
    const float lo_h  = bas_h + fminf(a11 * chl, a11 * chh) + fminf(a12 * cwl, a12 * cwh);
    const float hi_h  = bas_h + fmaxf(a11 * chl, a11 * chh) + fmaxf(a12 * cwl, a12 * cwh);

    // 0.5 guard >> fp discrepancy (~1e-4) between extrema and fma chains.
    const bool fast = (lo_d > 0.5f) & (hi_d < 190.5f) &
                      (lo_h > 0.5f) & (hi_h < 190.5f);

    if (fast) {
        // ---- fast path: d,h interior; w fully general ----
#pragma unroll
        for (int j = 0; j < UH; j++) {
            const float fj = (float)j;
            const float ldv = fmaf(a01, fj, ld0);
            const float lhv = fmaf(a11, fj, lh0);
            const float lwv = fmaf(a21, fj, lw0);

            const int   id = (int)ldv;  const float td = ldv - (float)id;
            const int   ih = (int)lhv;  const float th = lhv - (float)ih;

            const float sw = fminf(fmaxf(lwv, 0.f), maxl);
            const int   iw = (int)sw;
            const float tw = sw - (float)iw;
            const int   ow = (iw < DIM - 1) ? 1 : 0;

            const float* p  = vb + (id * SLAB + ih * DIM + iw);
            const float* p2 = p + ow;

            const float v000 = __ldg(p);
            const float v001 = __ldg(p2);
            const float v010 = __ldg(p  + DIM);
            const float v011 = __ldg(p2 + DIM);
            const float v100 = __ldg(p  + SLAB);
            const float v101 = __ldg(p2 + SLAB);
            const float v110 = __ldg(p  + SLAB + DIM);
            const float v111 = __ldg(p2 + SLAB + DIM);

            const float p00 = fmaf(tw, v001 - v000, v000);
            const float p01 = fmaf(tw, v011 - v010, v010);
            const float p10 = fmaf(tw, v101 - v100, v100);
            const float p11 = fmaf(tw, v111 - v110, v110);
            const float q0  = fmaf(th, p01 - p00, p00);
            const float q1  = fmaf(th, p11 - p10, p10);

            ob[j * DIM] = fmaf(td, q1 - q0, q0);
        }
    } else {
        // ---- general path: exact reference clamp semantics every dim ----
#pragma unroll
        for (int j = 0; j < UH; j++) {
            const float fj = (float)j;
            const float ldv = fmaf(a01, fj, ld0);
            const float lhv = fmaf(a11, fj, lh0);
            const float lwv = fmaf(a21, fj, lw0);

            const float sd = fminf(fmaxf(ldv, 0.f), maxl);
            const int   id = (int)sd;
            const float td = sd - (float)id;
            const int   od = (id < DIM - 1) ? SLAB : 0;

            const float sh = fminf(fmaxf(lhv, 0.f), maxl);
            const int   ih = (int)sh;
            const float th = sh - (float)ih;
            const int   oh = (ih < DIM - 1) ? DIM : 0;

            const float sw = fminf(fmaxf(lwv, 0.f), maxl);
            const int   iw = (int)sw;
            const float tw = sw - (float)iw;
            const int   ow = (iw < DIM - 1) ? 1 : 0;

            const float* p = vb + (id * SLAB + ih * DIM + iw);

            const float v000 = __ldg(p);
            const float v001 = __ldg(p + ow);
            const float v010 = __ldg(p + oh);
            const float v011 = __ldg(p + oh + ow);
            const float* q = p + od;
            const float v100 = __ldg(q);
            const float v101 = __ldg(q + ow);
            const float v110 = __ldg(q + oh);
            const float v111 = __ldg(q + oh + ow);

            const float p00 = fmaf(tw, v001 - v000, v000);
            const float p01 = fmaf(tw, v011 - v010, v010);
            const float p10 = fmaf(tw, v101 - v100, v100);
            const float p11 = fmaf(tw, v111 - v110, v110);
            const float q0  = fmaf(th, p01 - p00, p00);
            const float q1  = fmaf(th, p11 - p10, p10);

            ob[j * DIM] = fmaf(td, q1 - q0, q0);
        }
    }
}

extern "C" void kernel_launch(void* const* d_in, const int* in_sizes, int n_in,
                              void* d_out, int out_size)
{
    const float* vol = (const float*)d_in[0];
    const float* aff = (const float*)d_in[1];
    float* out = (float*)d_out;

    dim3 grid(DIM / UH, DIM, BATCH);   // (32, 192, 2)
    dim3 block(DIM);                   // 192 threads, warp = 32 consecutive w
    st_warp_u6<<<grid, block>>>(vol, aff, out);
}